// round 3
// baseline (speedup 1.0000x reference)
#include <cuda_runtime.h>
#include <math.h>

#define BB    256
#define T2V   1026
#define TP1   1025
#define SSV   1024
#define NVOC  35
#define H7    224
#define HN    (BB*SSV)          /* 262144 valid sampling rows */
#define EPSV  2.220446049250313e-16f
#define LOG2E 1.4426950408889634f
#define LN2   0.6931471805599453f

// ---------------- device scratch ----------------
static __device__ float g_prex[NVOC * H7];
static __device__ float g_intA[BB], g_intB[BB];
static __device__ float g_mskA[BB], g_mskB[BB];
static __device__ float g_loglam[BB], g_nev[BB];

// ---------------- fast math ----------------
__device__ __forceinline__ float ex2f(float x){ float r; asm("ex2.approx.f32 %0,%1;":"=f"(r):"f"(x)); return r; }
__device__ __forceinline__ float lg2f(float x){ float r; asm("lg2.approx.f32 %0,%1;":"=f"(r):"f"(x)); return r; }
__device__ __forceinline__ float rcpf(float x){ float r; asm("rcp.approx.f32 %0,%1;":"=f"(r):"f"(x)); return r; }
__device__ __forceinline__ float sig_fast(float x){ return rcpf(1.0f + ex2f(-x * LOG2E)); }
__device__ __forceinline__ float tanh_fast(float x){ return fmaf(2.0f, rcpf(1.0f + ex2f(-2.0f * LOG2E * x)), -1.0f); }
__device__ __forceinline__ float softplus_fast(float x){
    return fmaxf(x, 0.0f) + lg2f(1.0f + ex2f(-fabsf(x) * LOG2E)) * LN2;
}
// softplus(x)/ln2  (delta kept in log2 domain)
__device__ __forceinline__ float softplus_log2(float x){
    return fmaxf(x, 0.0f) * LOG2E + lg2f(1.0f + ex2f(-fabsf(x) * LOG2E));
}

// ---------------- kernel A: prex[v][j] = Emb[v]·Wx[:,j] + b[j] ------------
__global__ void k_prex(const float* __restrict__ Emb,
                       const float* __restrict__ W,
                       const float* __restrict__ bias) {
    int v = blockIdx.x;
    int j = threadIdx.x;              // 224 threads
    float acc = bias[j];
    #pragma unroll
    for (int k = 0; k < 32; k++)
        acc += Emb[v * 32 + k] * W[k * H7 + j];
    g_prex[v * H7 + j] = acc;
}

// ---------------- fused scan + sampler + target, one CTA per batch --------
// warps 0-6: gate slices (thread j = gate-major index 0..223)
// warp 7   : sampler consumer (lags producer by 1 step)
// warp 8   : target-loglambda consumer (lags by 1 step)
__global__ void __launch_bounds__(288, 2)
k_scan(const int*   __restrict__ event,
       const float* __restrict__ dtime,
       const float* __restrict__ W,
       const float* __restrict__ Wl,
       const float* __restrict__ dts,
       const float* __restrict__ mask,
       float*       __restrict__ lam_out) {
    const int b    = blockIdx.x;
    const int tid  = threadIdx.x;
    const int w    = tid >> 5;
    const int lane = tid & 31;

    __shared__ float prex_sh[NVOC * H7];   // 31.4 KB
    __shared__ float act[2][H7];           // double-buffered activations
    __shared__ float ring[4][5][32];       // per-step state: c,cb,L,o,h
    __shared__ float wlp[32 * 33];         // padded Wl for target warp
    __shared__ float shch[32];             // sampler transpose

    for (int i = tid; i < NVOC * H7; i += 288) prex_sh[i] = g_prex[i];
    for (int i = tid; i < 1024; i += 288)      wlp[(i >> 5) * 33 + (i & 31)] = Wl[i];

    const int*   evrow = event + b * T2V;
    const float* dtrow = dtime + b * T2V;

    // ---- gate-warp state ----
    float wcol[32];
    float h_reg = 0.0f, cm = 0.0f, cbm = 0.0f;
    int   ev = 0; float dtn = 0.0f;
    if (w < 7) {
        #pragma unroll
        for (int k = 0; k < 32; k++) wcol[k] = W[(32 + k) * H7 + tid];
        ev  = evrow[0];
        dtn = dtrow[1];
    }

    // ---- sampler-warp state ----
    float wle[32];
    float accLam0 = 0.f, accLam1 = 0.f, accM0 = 0.f, accM1 = 0.f;
    if (w == 7) {
        #pragma unroll
        for (int k = 0; k < 32; k++) wle[k] = Wl[lane * 32 + k];
    }
    // ---- target-warp state ----
    float accL = 0.f, accN = 0.f;

    __syncthreads();

    for (int t = 0; t <= TP1; t++) {
        // ---------- phase 1: pre-activations (gates only, t < TP1) ----------
        if (w < 7 && t < TP1) {
            float pre = prex_sh[ev * H7 + tid];
            float a0 = 0.f, a1 = 0.f, a2 = 0.f, a3 = 0.f;
            #pragma unroll
            for (int k = 0; k < 32; k += 4) {
                float h0 = __shfl_sync(0xffffffffu, h_reg, k);
                float h1 = __shfl_sync(0xffffffffu, h_reg, k + 1);
                float h2 = __shfl_sync(0xffffffffu, h_reg, k + 2);
                float h3 = __shfl_sync(0xffffffffu, h_reg, k + 3);
                a0 = fmaf(h0, wcol[k],     a0);
                a1 = fmaf(h1, wcol[k + 1], a1);
                a2 = fmaf(h2, wcol[k + 2], a2);
                a3 = fmaf(h3, wcol[k + 3], a3);
            }
            pre += (a0 + a1) + (a2 + a3);

            float a;
            if (w == 2)      a = tanh_fast(pre);      // z
            else if (w == 6) a = softplus_log2(pre);  // delta in log2 domain
            else             a = sig_fast(pre);       // i,f,o,ib,fb
            act[t & 1][tid] = a;

            ev = evrow[t + 1 <= TP1 ? t + 1 : TP1];   // prefetch
        }
        __syncthreads();

        // ---------- phase 2 / consumers ----------
        if (w < 7) {
            if (t < TP1) {
                const float* A = act[t & 1];
                float iv  = A[lane];
                float fv  = A[32  + lane];
                float zv  = A[64  + lane];
                float ov  = A[96  + lane];
                float ibv = A[128 + lane];
                float fbv = A[160 + lane];
                float L   = A[192 + lane];

                float c  = fmaf(fv,  cm,  iv  * zv);
                float cb = fmaf(fbv, cbm, ibv * zv);
                float e  = ex2f(-L * dtn);
                float cn = fmaf(c - cb, e, cb);
                float h  = ov * tanh_fast(cn);

                if (w == 0) {
                    int s = t & 3;
                    ring[s][0][lane] = c;
                    ring[s][1][lane] = cb;
                    ring[s][2][lane] = L;
                    ring[s][3][lane] = ov;
                    ring[s][4][lane] = h;
                }
                h_reg = h; cm = cn; cbm = cb;
                dtn = dtrow[t + 2 <= T2V - 1 ? t + 2 : T2V - 1];
            }
        } else if (w == 7) {
            if (t > 0) {
                int tp = t - 1;
                int f  = b * TP1 + tp;
                if (f < HN) {
                    int s = tp & 3;
                    float c  = ring[s][0][lane];
                    float cb = ring[s][1][lane];
                    float L  = ring[s][2][lane];
                    float o  = ring[s][3][lane];
                    float dtv = dts[f];
                    float e  = ex2f(-L * dtv);
                    float cd = fmaf(c - cb, e, cb);
                    float ch = o * tanh_fast(cd);
                    shch[lane] = ch;
                    __syncwarp();
                    float d0 = 0.f, d1 = 0.f, d2 = 0.f, d3 = 0.f;
                    #pragma unroll
                    for (int q = 0; q < 8; q++) {
                        float4 c4 = ((const float4*)shch)[q];   // broadcast
                        d0 = fmaf(c4.x, wle[4 * q + 0], d0);
                        d1 = fmaf(c4.y, wle[4 * q + 1], d1);
                        d2 = fmaf(c4.z, wle[4 * q + 2], d2);
                        d3 = fmaf(c4.w, wle[4 * q + 3], d3);
                    }
                    float sp = softplus_fast((d0 + d1) + (d2 + d3));
                    lam_out[(size_t)f * 32 + lane] = sp;
                    float m = mask[f];
                    if (b + tp < 1024) { accLam0 += sp * m; if (lane == 0) accM0 += m; }
                    else               { accLam1 += sp * m; if (lane == 0) accM1 += m; }
                    __syncwarp();
                }
            }
        } else { // w == 8: target
            if (t > 0) {
                int tp  = t - 1;
                int s   = tp & 3;
                int tgt = evrow[tp + 1];
                bool mm = (tgt < 32);
                int  tt = mm ? tgt : 0;
                float p = ring[s][4][lane] * wlp[tt * 33 + lane];
                #pragma unroll
                for (int o = 16; o > 0; o >>= 1) p += __shfl_down_sync(0xffffffffu, p, o);
                if (lane == 0 && mm) {
                    accL += lg2f(softplus_fast(p) + EPSV) * LN2;
                    accN += 1.0f;
                }
            }
        }
    }

    // ---------- per-CTA epilogue ----------
    if (w == 7) {
        #pragma unroll
        for (int o = 16; o > 0; o >>= 1) {
            accLam0 += __shfl_down_sync(0xffffffffu, accLam0, o);
            accLam1 += __shfl_down_sync(0xffffffffu, accLam1, o);
        }
        if (lane == 0) {
            g_intA[b] = accLam0; g_intB[b] = accLam1;
            g_mskA[b] = accM0;   g_mskB[b] = accM1;
        }
    } else if (w == 8 && lane == 0) {
        g_loglam[b] = accL;
        g_nev[b]    = accN;
    }
}

// ---------------- final: stitch integral groups + reduce scalars ----------
__global__ void __launch_bounds__(256)
k_final(const float* __restrict__ dur, float* __restrict__ out) {
    const int bb = threadIdx.x;     // one thread per group
    __shared__ float red[8];

    float lamsum = g_intA[bb] + (bb > 0 ? g_intB[bb - 1] : 0.0f);
    float msum   = g_mskA[bb] + (bb > 0 ? g_mskB[bb - 1] : 0.0f);
    float integ  = __fdividef(lamsum, msum) * dur[bb];
    float lp = g_loglam[bb] - integ;
    float nv = g_nev[bb];

    #pragma unroll
    for (int o = 16; o > 0; o >>= 1) lp += __shfl_down_sync(0xffffffffu, lp, o);
    int wid = threadIdx.x >> 5, lid = threadIdx.x & 31;
    if (lid == 0) red[wid] = lp;
    __syncthreads();
    if (wid == 0) {
        float v = (lid < 8) ? red[lid] : 0.0f;
        #pragma unroll
        for (int o = 4; o > 0; o >>= 1) v += __shfl_down_sync(0xffffffffu, v, o);
        if (lid == 0) out[0] = -v;
    }
    __syncthreads();
    #pragma unroll
    for (int o = 16; o > 0; o >>= 1) nv += __shfl_down_sync(0xffffffffu, nv, o);
    if (lid == 0) red[wid] = nv;
    __syncthreads();
    if (wid == 0) {
        float v = (lid < 8) ? red[lid] : 0.0f;
        #pragma unroll
        for (int o = 4; o > 0; o >>= 1) v += __shfl_down_sync(0xffffffffu, v, o);
        if (lid == 0) out[1] = v;
    }
}

// ---------------- launch ----------------
extern "C" void kernel_launch(void* const* d_in, const int* in_sizes, int n_in,
                              void* d_out, int out_size) {
    const int*   event = (const int*)  d_in[0];
    const float* dtime = (const float*)d_in[1];
    const float* dur   = (const float*)d_in[2];
    const float* dts   = (const float*)d_in[3];
    // d_in[4] = index_of_hidden_sampling (unused by the reference)
    const float* mask  = (const float*)d_in[5];
    const float* Emb   = (const float*)d_in[6];
    const float* W     = (const float*)d_in[7];
    const float* bias  = (const float*)d_in[8];
    const float* Wl    = (const float*)d_in[9];

    float* out = (float*)d_out;
    long long lam_elems = (long long)HN * 32;
    long long lamoff = (long long)out_size - lam_elems;
    if (lamoff < 0) lamoff = 0;
    float* lam_out = out + lamoff;

    k_prex <<<NVOC, H7>>>(Emb, W, bias);
    k_scan <<<BB, 288>>>(event, dtime, W, Wl, dts, mask, lam_out);
    k_final<<<1, 256>>>(dur, out);
}